// round 3
// baseline (speedup 1.0000x reference)
#include <cuda_runtime.h>
#include <cstdint>

// MultiStepIFNode: T=16 integrate-and-fire, pure HBM streaming (256 MiB in,
// 256 MiB out). R3 changes vs R2:
//  - Persistent grid-stride kernel: grid = 444 CTAs (148 SMs x occ 3)
//    instead of 4096. Removes ~8 wave transitions (~2360 cyc each) and the
//    per-wave MLP drain/ramp; the load pipeline stays full for the whole
//    kernel. Tail straggle paid once.
//  - Keeps R2's 8-load front-batch (MLP=8/thread) and __ldcs/__stcs
//    streaming hints.

static constexpr int T_STEPS = 16;
static constexpr int T_HALF  = 8;
static constexpr int GRID    = 444;   // 148 SMs * 3 CTAs/SM (regs=56 @ bounds(256,3))

__global__ __launch_bounds__(256, 3) void if_multistep_kernel(
    const float4* __restrict__ x,   // T * n4 float4s
    float4* __restrict__ out,       // T * n4 float4s
    int n4)                         // float4s per timestep (N/4)
{
    const int stride = gridDim.x * blockDim.x;

    for (int i = blockIdx.x * blockDim.x + threadIdx.x; i < n4; i += stride) {
        float vx = 0.f, vy = 0.f, vz = 0.f, vw = 0.f;

        #pragma unroll
        for (int half = 0; half < 2; half++) {
            // Front-batch 8 independent loads -> 8 outstanding DRAM requests
            float4 xt[T_HALF];
            #pragma unroll
            for (int t = 0; t < T_HALF; t++) {
                xt[t] = __ldcs(&x[(size_t)(half * T_HALF + t) * n4 + i]);
            }

            #pragma unroll
            for (int t = 0; t < T_HALF; t++) {
                vx += xt[t].x;
                vy += xt[t].y;
                vz += xt[t].z;
                vw += xt[t].w;

                float4 s;
                s.x = (vx >= 1.0f) ? 1.0f : 0.0f;
                s.y = (vy >= 1.0f) ? 1.0f : 0.0f;
                s.z = (vz >= 1.0f) ? 1.0f : 0.0f;
                s.w = (vw >= 1.0f) ? 1.0f : 0.0f;

                vx -= s.x;
                vy -= s.y;
                vz -= s.z;
                vw -= s.w;

                __stcs(&out[(size_t)(half * T_HALF + t) * n4 + i], s);
            }
        }
    }
}

extern "C" void kernel_launch(void* const* d_in, const int* in_sizes, int n_in,
                              void* d_out, int out_size)
{
    const float4* x = (const float4*)d_in[0];
    float4* out = (float4*)d_out;

    int n_per_step = out_size / T_STEPS;   // 4,194,304
    int n4 = n_per_step / 4;               // 1,048,576

    if_multistep_kernel<<<GRID, 256>>>(x, out, n4);
}

// round 4
// speedup vs baseline: 1.1057x; 1.1057x over previous
#include <cuda_runtime.h>
#include <cstdint>

// MultiStepIFNode: T=16 integrate-and-fire, pure HBM streaming (256 MiB in,
// 256 MiB out). R4 = R2 shape (grid=4096, 8-load front-batch, streaming
// hints) with occupancy bound raised 3 -> 4 CTAs/SM: kernel uses 56 regs,
// which fits 4 CTAs (64 regs each). In-flight loads/SM: 192 -> 256.
// R3's persistent-grid experiment regressed (chip-level concurrency is the
// binding resource, not wave transitions) and is reverted.

static constexpr int T_STEPS = 16;
static constexpr int T_HALF  = 8;

__global__ __launch_bounds__(256, 4) void if_multistep_kernel(
    const float4* __restrict__ x,   // T * n4 float4s
    float4* __restrict__ out,       // T * n4 float4s
    int n4)                         // float4s per timestep (N/4)
{
    int i = blockIdx.x * blockDim.x + threadIdx.x;
    if (i >= n4) return;

    float vx = 0.f, vy = 0.f, vz = 0.f, vw = 0.f;

    #pragma unroll
    for (int half = 0; half < 2; half++) {
        // Front-batch 8 independent loads -> 8 outstanding DRAM requests
        float4 xt[T_HALF];
        #pragma unroll
        for (int t = 0; t < T_HALF; t++) {
            xt[t] = __ldcs(&x[(size_t)(half * T_HALF + t) * n4 + i]);
        }

        #pragma unroll
        for (int t = 0; t < T_HALF; t++) {
            vx += xt[t].x;
            vy += xt[t].y;
            vz += xt[t].z;
            vw += xt[t].w;

            float4 s;
            s.x = (vx >= 1.0f) ? 1.0f : 0.0f;
            s.y = (vy >= 1.0f) ? 1.0f : 0.0f;
            s.z = (vz >= 1.0f) ? 1.0f : 0.0f;
            s.w = (vw >= 1.0f) ? 1.0f : 0.0f;

            vx -= s.x;
            vy -= s.y;
            vz -= s.z;
            vw -= s.w;

            __stcs(&out[(size_t)(half * T_HALF + t) * n4 + i], s);
        }
    }
}

extern "C" void kernel_launch(void* const* d_in, const int* in_sizes, int n_in,
                              void* d_out, int out_size)
{
    const float4* x = (const float4*)d_in[0];
    float4* out = (float4*)d_out;

    int n_per_step = out_size / T_STEPS;   // 4,194,304
    int n4 = n_per_step / 4;               // 1,048,576

    const int threads = 256;
    int blocks = (n4 + threads - 1) / threads;
    if_multistep_kernel<<<blocks, threads>>>(x, out, n4);
}

// round 5
// speedup vs baseline: 1.1151x; 1.0086x over previous
#include <cuda_runtime.h>
#include <cstdint>

// MultiStepIFNode: T=16 integrate-and-fire, pure HBM streaming (256 MiB in,
// 256 MiB out). Pinned at ~75.5us kernel / 80% DRAM-active across R2/R4
// (supply-side knobs exhausted). R5 targets DRAM bus turnaround instead:
// front-batch ALL 16 timestep loads per thread (16 LDG.128 back-to-back),
// then compute+store all 16. Doubles same-direction run length vs R2's
// 8/8 interleave. launch_bounds(256,2) -> 128-reg budget for the 64-reg
// data batch, no spills. If neutral, ~6.4 TB/s is the mixed-stream ceiling
// and the R2 shape is final.

static constexpr int T_STEPS = 16;

__global__ __launch_bounds__(256, 2) void if_multistep_kernel(
    const float4* __restrict__ x,   // T * n4 float4s
    float4* __restrict__ out,       // T * n4 float4s
    int n4)                         // float4s per timestep (N/4)
{
    int i = blockIdx.x * blockDim.x + threadIdx.x;
    if (i >= n4) return;

    // Front-batch all 16 loads: 16 outstanding LDG.128 per thread,
    // one contiguous read burst before any store issues.
    float4 xt[T_STEPS];
    #pragma unroll
    for (int t = 0; t < T_STEPS; t++) {
        xt[t] = __ldcs(&x[(size_t)t * n4 + i]);
    }

    float vx = 0.f, vy = 0.f, vz = 0.f, vw = 0.f;

    #pragma unroll
    for (int t = 0; t < T_STEPS; t++) {
        vx += xt[t].x;
        vy += xt[t].y;
        vz += xt[t].z;
        vw += xt[t].w;

        float4 s;
        s.x = (vx >= 1.0f) ? 1.0f : 0.0f;
        s.y = (vy >= 1.0f) ? 1.0f : 0.0f;
        s.z = (vz >= 1.0f) ? 1.0f : 0.0f;
        s.w = (vw >= 1.0f) ? 1.0f : 0.0f;

        vx -= s.x;
        vy -= s.y;
        vz -= s.z;
        vw -= s.w;

        __stcs(&out[(size_t)t * n4 + i], s);
    }
}

extern "C" void kernel_launch(void* const* d_in, const int* in_sizes, int n_in,
                              void* d_out, int out_size)
{
    const float4* x = (const float4*)d_in[0];
    float4* out = (float4*)d_out;

    int n_per_step = out_size / T_STEPS;   // 4,194,304
    int n4 = n_per_step / 4;               // 1,048,576

    const int threads = 256;
    int blocks = (n4 + threads - 1) / threads;
    if_multistep_kernel<<<blocks, threads>>>(x, out, n4);
}